// round 2
// baseline (speedup 1.0000x reference)
#include <cuda_runtime.h>
#include <cuda_pipeline.h>
#include <math.h>

#define B_ 16
#define A_ 256
#define N_ 64
#define G_ 64
#define F_ 128
#define ROWS_TOTAL (B_*A_)   // 4096

// scratch for y = x @ w_in2f  (2 MB, static device array: allocation-free)
__device__ float g_y[ROWS_TOTAL * F_];

__device__ __forceinline__ float sspf(float x) {
    float ax = fabsf(x);
    return fmaxf(x, 0.0f) + __logf(1.0f + __expf(-ax)) - 0.6931471805599453f;
}

// ---- packed fp32x2 helpers (FFMA2 path; ptxas never emits these from C++) ----
typedef unsigned long long u64;

__device__ __forceinline__ u64 splat2(float x) {
    u64 r;
    asm("mov.b64 %0, {%1, %1};" : "=l"(r) : "f"(x));
    return r;
}
__device__ __forceinline__ void ffma2(u64& d, u64 a, u64 b) {
    asm("fma.rn.f32x2 %0, %1, %2, %0;" : "+l"(d) : "l"(a), "l"(b));
}
__device__ __forceinline__ float2 unpack2(u64 v) {
    float2 f;
    asm("mov.b64 {%0, %1}, %2;" : "=f"(f.x), "=f"(f.y) : "l"(v));
    return f;
}

// ---------------------------------------------------------------------------
// Kernel 1: y[row][f] = sum_k x[row][k] * w_in2f[k][f]
// ---------------------------------------------------------------------------
__global__ void in2f_kernel(const float* __restrict__ x,
                            const float* __restrict__ w) {
    __shared__ float sx[F_];
    int row = blockIdx.x;
    int t = threadIdx.x;  // 128 threads
    sx[t] = x[row * F_ + t];
    __syncthreads();
    float acc = 0.f;
#pragma unroll 8
    for (int k = 0; k < F_; k++) {
        acc += sx[k] * w[k * F_ + t];
    }
    g_y[row * F_ + t] = acc;
}

// ---------------------------------------------------------------------------
// Kernel 2: fused CFConv per atom (k-split 2 groups, 8x8 tiles, FFMA2)
// ---------------------------------------------------------------------------

// shared layout (float offsets)
#define SA_OFF    0                      // [64][68]  f_ij row-major, pad 68
#define SW1_OFF   (SA_OFF   + 64*68)     // [64][128] fw1
#define SH_OFF    (SW1_OFF  + 64*128)    // [64][132] H row-major, pad 132
#define SW2_OFF   (SH_OFF   + 64*132)    // [128][128] fw2
#define SY_OFF    (SW2_OFF  + 128*128)   // [64][128] gathered y rows
#define SP_OFF    (SY_OFF   + 64*128)    // [64][128] k-split partial buffer
#define SRED_OFF  (SP_OFF   + 64*128)    // [8][128] row reduction
#define SB1_OFF   (SRED_OFF + 8*128)     // [128]
#define SB2_OFF   (SB1_OFF  + 128)       // [128]
#define SCC_OFF   (SB2_OFF  + 128)       // [64]
#define SACC_OFF  (SCC_OFF  + 64)        // [128]
#define SF_OFF    (SACC_OFF + 128)       // [2][128] f2out partials
#define SMEM_FLOATS (SF_OFF + 256)
#define SMEM_BYTES  (SMEM_FLOATS * 4)    // 221952 B

__global__ __launch_bounds__(256, 1)
void cfconv_kernel(const float* __restrict__ r_ij,
                   const float* __restrict__ f_ij,
                   const int*   __restrict__ neighbors,
                   const float* __restrict__ pmask,
                   const float* __restrict__ fw1,
                   const float* __restrict__ fb1,
                   const float* __restrict__ fw2,
                   const float* __restrict__ fb2,
                   const float* __restrict__ w_f2out,
                   const float* __restrict__ b_f2out,
                   float* __restrict__ out) {
    extern __shared__ float sm[];
    float* sA   = sm + SA_OFF;
    float* sW1  = sm + SW1_OFF;
    float* sH   = sm + SH_OFF;
    float* sW2  = sm + SW2_OFF;
    float* sY   = sm + SY_OFF;
    float* sP   = sm + SP_OFF;
    float* sRed = sm + SRED_OFF;
    float* sB1  = sm + SB1_OFF;
    float* sB2  = sm + SB2_OFF;
    float* sCC  = sm + SCC_OFF;
    float* sAcc = sm + SACC_OFF;
    float* sF   = sm + SF_OFF;

    const int cta = blockIdx.x;     // b*A + a
    const int tid = threadIdx.x;
    const int b   = cta >> 8;       // A_ = 256

    // ---- async group A: f_ij, fw1, fb1 ----
    {
        const float* fsrc = f_ij + (size_t)cta * (N_ * G_);
#pragma unroll
        for (int q = 0; q < 4; q++) {
            int f4 = q * 256 + tid;          // 0..1023 float4s
            int n  = f4 >> 4;                // row
            int g4 = f4 & 15;                // float4 within row
            __pipeline_memcpy_async(sA + n * 68 + g4 * 4, fsrc + f4 * 4, 16);
        }
#pragma unroll
        for (int q = 0; q < 8; q++) {
            int f4 = q * 256 + tid;
            __pipeline_memcpy_async(sW1 + f4 * 4, fw1 + f4 * 4, 16);
        }
        if (tid < 32) __pipeline_memcpy_async(sB1 + tid * 4, fb1 + tid * 4, 16);
        __pipeline_commit();
    }
    // ---- async group B: fw2, gathered y, fb2 ----
    {
#pragma unroll
        for (int q = 0; q < 16; q++) {
            int f4 = q * 256 + tid;
            __pipeline_memcpy_async(sW2 + f4 * 4, fw2 + f4 * 4, 16);
        }
        int n  = tid >> 2;
        int ch = tid & 3;
        int nb = neighbors[cta * N_ + n];
        const float* src = g_y + (size_t)(b * A_ + nb) * F_ + ch * 32;
        float* dst = sY + n * F_ + ch * 32;
#pragma unroll
        for (int q = 0; q < 8; q++) {
            __pipeline_memcpy_async(dst + q * 4, src + q * 4, 16);
        }
        if (tid < 32) __pipeline_memcpy_async(sB2 + tid * 4, fb2 + tid * 4, 16);
        __pipeline_commit();
    }

    if (tid < 64) {
        float r = r_ij[cta * N_ + tid];
        float m = pmask[cta * N_ + tid];
        float c = (r < 5.0f) ? 0.5f * (__cosf(r * 0.6283185307179586f) + 1.0f) : 0.0f;
        sCC[tid] = c * m;
    }
    __pipeline_wait_prior(1);   // group A landed
    __syncthreads();

    const int kg   = tid >> 7;       // k-split group 0/1
    const int t128 = tid & 127;
    const int tr   = t128 >> 4;      // 0..7  -> rows tr*8..tr*8+7
    const int tc   = t128 & 15;      // 0..15 -> cols tc*8..tc*8+7
    const int r0   = tr * 8;
    const int c0   = tc * 8;

    u64 acc[8][4];
#pragma unroll
    for (int i = 0; i < 8; i++)
#pragma unroll
        for (int j = 0; j < 4; j++) acc[i][j] = 0ull;

    // ---- GEMM1: H_partial = f_ij(kg half) @ fw1, k in [kg*32, kg*32+32) ----
    {
        const int kb = kg * 32;
#pragma unroll 2
        for (int k = 0; k < 32; k++) {
            const int kk = kb + k;
            const ulonglong2* bp = (const ulonglong2*)(sW1 + kk * F_ + c0);
            ulonglong2 b01 = bp[0], b23 = bp[1];
            u64 bb[4] = {b01.x, b01.y, b23.x, b23.y};
#pragma unroll
            for (int i = 0; i < 8; i++) {
                u64 av = splat2(sA[(r0 + i) * 68 + kk]);
#pragma unroll
                for (int j = 0; j < 4; j++) ffma2(acc[i][j], av, bb[j]);
            }
        }
    }
    // combine: group1 dumps partial, group0 adds + bias + ssp -> sH
    if (kg == 1) {
#pragma unroll
        for (int i = 0; i < 8; i++) {
            ulonglong2* p = (ulonglong2*)(sP + (r0 + i) * F_ + c0);
            p[0] = make_ulonglong2(acc[i][0], acc[i][1]);
            p[1] = make_ulonglong2(acc[i][2], acc[i][3]);
        }
    }
    __syncthreads();
    if (kg == 0) {
#pragma unroll
        for (int i = 0; i < 8; i++) {
            const int r = r0 + i;
            const float* pr = sP + r * F_ + c0;
            float* hr = sH + r * 132 + c0;
#pragma unroll
            for (int j = 0; j < 4; j++) {
                float2 a2 = unpack2(acc[i][j]);
                hr[2*j]   = sspf(a2.x + pr[2*j]   + sB1[c0 + 2*j]);
                hr[2*j+1] = sspf(a2.y + pr[2*j+1] + sB1[c0 + 2*j+1]);
            }
        }
    }
    __pipeline_wait_prior(0);   // group B landed (sW2, sY, sB2)
    __syncthreads();

    // ---- GEMM2: W_partial = H @ fw2, k in [kg*64, kg*64+64) ----
#pragma unroll
    for (int i = 0; i < 8; i++)
#pragma unroll
        for (int j = 0; j < 4; j++) acc[i][j] = 0ull;
    {
        const int kb = kg * 64;
#pragma unroll 2
        for (int k = 0; k < 64; k++) {
            const int kk = kb + k;
            const ulonglong2* bp = (const ulonglong2*)(sW2 + kk * F_ + c0);
            ulonglong2 b01 = bp[0], b23 = bp[1];
            u64 bb[4] = {b01.x, b01.y, b23.x, b23.y};
#pragma unroll
            for (int i = 0; i < 8; i++) {
                u64 av = splat2(sH[(r0 + i) * 132 + kk]);
#pragma unroll
                for (int j = 0; j < 4; j++) ffma2(acc[i][j], av, bb[j]);
            }
        }
    }
    // combine + epilogue: W = acc0+acc1+fb2; p[c] = sum_r W*cc[r]*y[r][c]
    if (kg == 1) {
#pragma unroll
        for (int i = 0; i < 8; i++) {
            ulonglong2* p = (ulonglong2*)(sP + (r0 + i) * F_ + c0);
            p[0] = make_ulonglong2(acc[i][0], acc[i][1]);
            p[1] = make_ulonglong2(acc[i][2], acc[i][3]);
        }
    }
    __syncthreads();
    if (kg == 0) {
        float p[8];
#pragma unroll
        for (int j = 0; j < 8; j++) p[j] = 0.f;
#pragma unroll
        for (int i = 0; i < 8; i++) {
            const int r = r0 + i;
            const float ccv = sCC[r];
            const float* pr = sP + r * F_ + c0;
            const float* yr = sY + r * F_ + c0;
#pragma unroll
            for (int j = 0; j < 4; j++) {
                float2 a2 = unpack2(acc[i][j]);
                float w0 = a2.x + pr[2*j]   + sB2[c0 + 2*j];
                float w1 = a2.y + pr[2*j+1] + sB2[c0 + 2*j+1];
                p[2*j]   += w0 * ccv * yr[2*j];
                p[2*j+1] += w1 * ccv * yr[2*j+1];
            }
        }
        float4* rp = (float4*)(sRed + tr * F_ + c0);
        rp[0] = make_float4(p[0], p[1], p[2], p[3]);
        rp[1] = make_float4(p[4], p[5], p[6], p[7]);
    }
    __syncthreads();
    if (tid < F_) {
        float s = 0.f;
#pragma unroll
        for (int q = 0; q < 8; q++) s += sRed[q * F_ + tid];
        sAcc[tid] = s;
    }
    __syncthreads();

    // ---- f2out (split-k over 256 threads): out = ssp(agg @ w_f2out + b) ----
    {
        const int half = tid >> 7;
        const int f    = tid & 127;
        float v = 0.f;
        const float* wp = w_f2out + (size_t)half * 64 * F_ + f;
        const float* ap = sAcc + half * 64;
#pragma unroll 8
        for (int k = 0; k < 64; k++) {
            v += ap[k] * wp[k * F_];
        }
        sF[half * F_ + f] = v;
    }
    __syncthreads();
    if (tid < F_) {
        float v = sF[tid] + sF[F_ + tid] + b_f2out[tid];
        out[(size_t)cta * F_ + tid] = sspf(v);
    }
}

// ---------------------------------------------------------------------------
extern "C" void kernel_launch(void* const* d_in, const int* in_sizes, int n_in,
                              void* d_out, int out_size) {
    const float* x        = (const float*)d_in[0];
    const float* r_ij     = (const float*)d_in[1];
    const float* f_ij     = (const float*)d_in[2];
    const int*   neighbors= (const int*)  d_in[3];
    const float* pmask    = (const float*)d_in[4];
    const float* fw1      = (const float*)d_in[5];
    const float* fb1      = (const float*)d_in[6];
    const float* fw2      = (const float*)d_in[7];
    const float* fb2      = (const float*)d_in[8];
    const float* w_in2f   = (const float*)d_in[9];
    const float* w_f2out  = (const float*)d_in[10];
    const float* b_f2out  = (const float*)d_in[11];
    float* out = (float*)d_out;

    cudaFuncSetAttribute(cfconv_kernel,
                         cudaFuncAttributeMaxDynamicSharedMemorySize, SMEM_BYTES);

    in2f_kernel<<<ROWS_TOTAL, F_>>>(x, w_in2f);
    cfconv_kernel<<<ROWS_TOTAL, 256, SMEM_BYTES>>>(
        r_ij, f_ij, neighbors, pmask, fw1, fb1, fw2, fb2,
        w_f2out, b_f2out, out);
}

// round 4
// speedup vs baseline: 2.2038x; 2.2038x over previous
#include <cuda_runtime.h>
#include <cuda_bf16.h>
#include <math.h>
#include <stdint.h>

#define B_ 16
#define A_ 256
#define NN 64
#define G_ 64
#define F_ 128
#define ROWS_TOTAL (B_*A_)   // 4096

// static device scratch (allocation-free)
__device__ float g_y[ROWS_TOTAL * F_];     // in2f output
__device__ float g_agg[ROWS_TOTAL * F_];   // aggregate before f2out
// MMA-ready weight images: [n][k-word] packed bf16x2 (hi and lo splits)
__device__ __align__(1024) uint32_t g_w1h[128 * 36];
__device__ __align__(1024) uint32_t g_w1l[128 * 36];
__device__ __align__(1024) uint32_t g_w2h[128 * 68];
__device__ __align__(1024) uint32_t g_w2l[128 * 68];

__device__ __forceinline__ float sspf(float x) {
    float ax = fabsf(x);
    return fmaxf(x, 0.0f) + __logf(1.0f + __expf(-ax)) - 0.6931471805599453f;
}

// split a pair of fp32 into packed bf16x2 hi and lo words
__device__ __forceinline__ void split2(float x, float y, uint32_t& hi, uint32_t& lo) {
    __nv_bfloat16 hx = __float2bfloat16(x);
    __nv_bfloat16 hy = __float2bfloat16(y);
    float rx = x - __bfloat162float(hx);
    float ry = y - __bfloat162float(hy);
    __nv_bfloat16 lx = __float2bfloat16(rx);
    __nv_bfloat16 ly = __float2bfloat16(ry);
    hi = (uint32_t)__bfloat16_as_ushort(hx) | ((uint32_t)__bfloat16_as_ushort(hy) << 16);
    lo = (uint32_t)__bfloat16_as_ushort(lx) | ((uint32_t)__bfloat16_as_ushort(ly) << 16);
}

// ---------------- mbarrier / bulk-copy PTX (sm_90-era, compiles for sm_103) ----
#define MB_INIT(addr, cnt) \
    asm volatile("mbarrier.init.shared.b64 [%0], %1;" :: "r"(addr), "r"((uint32_t)(cnt)) : "memory")
#define MB_INVAL(addr) \
    asm volatile("mbarrier.inval.shared.b64 [%0];" :: "r"(addr) : "memory")
#define MB_EXPECT_TX(addr, bytes) \
    asm volatile("mbarrier.arrive.expect_tx.shared.b64 _, [%0], %1;" :: "r"(addr), "r"((uint32_t)(bytes)) : "memory")
#define MB_WAIT(addr, phase) do { \
    asm volatile("{ .reg .pred P1;\n\t" \
        "WL_%=:\n\t" \
        "mbarrier.try_wait.parity.acquire.cta.shared::cta.b64 P1, [%0], %1, 0x989680;\n\t" \
        "@P1 bra.uni WD_%=;\n\t" \
        "bra.uni WL_%=;\n\t" \
        "WD_%=: }" :: "r"(addr), "r"((uint32_t)(phase)) : "memory"); \
} while (0)
#define BULK_G2S(dst, src, bytes, mbar) \
    asm volatile("cp.async.bulk.shared::cta.global.mbarrier::complete_tx::bytes [%0], [%1], %2, [%3];" \
        :: "r"(dst), "l"(src), "r"((uint32_t)(bytes)), "r"(mbar) : "memory")
#define FENCE_PROXY() asm volatile("fence.proxy.async.shared::cta;" ::: "memory")

__device__ __forceinline__ uint32_t smem_u32(const void* p) {
    uint32_t a;
    asm("{ .reg .u64 t; cvta.to.shared.u64 t, %1; cvt.u32.u64 %0, t; }"
        : "=r"(a) : "l"(p));
    return a;
}

// m16n8k16 bf16 MMA, fp32 accumulate
__device__ __forceinline__ void mma_bf16(float c[4], const uint32_t a[4], const uint32_t b[2]) {
    asm volatile("mma.sync.aligned.m16n8k16.row.col.f32.bf16.bf16.f32 "
        "{%0,%1,%2,%3}, {%4,%5,%6,%7}, {%8,%9}, {%0,%1,%2,%3};"
        : "+f"(c[0]), "+f"(c[1]), "+f"(c[2]), "+f"(c[3])
        : "r"(a[0]), "r"(a[1]), "r"(a[2]), "r"(a[3]), "r"(b[0]), "r"(b[1]));
}

// ---------------------------------------------------------------------------
// Prologue: build hi/lo bf16 weight images, layout [n][kword], word = (k=2c, 2c+1)
// ---------------------------------------------------------------------------
__global__ void weights_img_kernel(const float* __restrict__ fw1,
                                   const float* __restrict__ fw2) {
    int t = blockIdx.x * 256 + threadIdx.x;  // 12288 total
    if (t < 4096) {                 // w1: n = t>>5 (0..127), c = t&31 (k-words)
        int n = t >> 5, c = t & 31;
        float x = fw1[(2 * c) * F_ + n];
        float y = fw1[(2 * c + 1) * F_ + n];
        uint32_t hi, lo;
        split2(x, y, hi, lo);
        g_w1h[n * 36 + c] = hi;
        g_w1l[n * 36 + c] = lo;
    } else if (t < 12288) {         // w2: n = u>>6, c = u&63
        int u = t - 4096;
        int n = u >> 6, c = u & 63;
        float x = fw2[(2 * c) * F_ + n];
        float y = fw2[(2 * c + 1) * F_ + n];
        uint32_t hi, lo;
        split2(x, y, hi, lo);
        g_w2h[n * 68 + c] = hi;
        g_w2l[n * 68 + c] = lo;
    }
}

// ---------------------------------------------------------------------------
// Small fp32 GEMM (in2f / f2out): dst = act(bias + src @ w)
// ---------------------------------------------------------------------------
__global__ __launch_bounds__(256, 2)
void small_gemm(const float* __restrict__ src, const float* __restrict__ w,
                const float* __restrict__ bias, float* __restrict__ dst, int act) {
    __shared__ float sX[32 * 128];
    const int blk = blockIdx.x;
    const int tid = threadIdx.x;
    const float* s0 = src + (size_t)blk * 32 * F_;
#pragma unroll
    for (int q = 0; q < 16; q++) sX[q * 256 + tid] = s0[q * 256 + tid];
    __syncthreads();

    const int rg = tid >> 5, cg = tid & 31;
    float acc[4][4];
#pragma unroll
    for (int i = 0; i < 4; i++)
#pragma unroll
        for (int j = 0; j < 4; j++) acc[i][j] = 0.f;

#pragma unroll 4
    for (int k = 0; k < F_; k++) {
        float4 bv = *(const float4*)(w + k * F_ + cg * 4);
        float aa[4];
#pragma unroll
        for (int i = 0; i < 4; i++) aa[i] = sX[(rg * 4 + i) * F_ + k];
        float bb[4] = {bv.x, bv.y, bv.z, bv.w};
#pragma unroll
        for (int i = 0; i < 4; i++)
#pragma unroll
            for (int j = 0; j < 4; j++) acc[i][j] += aa[i] * bb[j];
    }
    float bb4[4] = {0.f, 0.f, 0.f, 0.f};
    if (bias) {
        float4 b4 = *(const float4*)(bias + cg * 4);
        bb4[0] = b4.x; bb4[1] = b4.y; bb4[2] = b4.z; bb4[3] = b4.w;
    }
#pragma unroll
    for (int i = 0; i < 4; i++) {
        int row = blk * 32 + rg * 4 + i;
        float o[4];
#pragma unroll
        for (int j = 0; j < 4; j++) {
            float v = acc[i][j] + bb4[j];
            o[j] = act ? sspf(v) : v;
        }
        *(float4*)(dst + (size_t)row * F_ + cg * 4) = make_float4(o[0], o[1], o[2], o[3]);
    }
}

// ---------------------------------------------------------------------------
// Main fused kernel: 2 atoms/CTA, bf16 hi/lo 3-MMA emulated GEMMs on tensor pipe
// ---------------------------------------------------------------------------
// smem word offsets
#define AF_H   0        // [128][36]  f_ij hi (bf16x2 words)
#define AF_L   4608     // [128][36]  f_ij lo
#define W1_H   9216     // [128][36]
#define W1_L   13824    // [128][36]     (union end 18432)
#define H_H    0        // [128][68]  H hi (aliases AF/W1 after GEMM1)
#define H_L    8704     // [128][68]
#define W2_H   18432    // [128][68]
#define W2_L   27136    // [128][68]
#define CCY    35840    // float [128 cols][132] : cc[n]*y[nbh[n]][col]
#define SB1    52736    // float [128]
#define SB2    52864    // float [128]
#define SCC    52992    // float [128]
#define SAGG   53120    // float [2][128]
#define MBAR   53376    // 2 mbarriers (4 words)
#define SMEM_WORDS 53384
#define SMEM_BYTES (SMEM_WORDS * 4)

// generic 3-MMA split GEMM over the CTA tile (M=128, N=128)
__device__ __forceinline__ void gemm_split(
    const uint32_t* __restrict__ Ah, const uint32_t* __restrict__ Al,
    const uint32_t* __restrict__ Bh, const uint32_t* __restrict__ Bl,
    int ld, int nk, int wm, int wn, int lane, float acc[16][4])
{
    const int g = lane >> 2, t = lane & 3;
    for (int ks = 0; ks < nk; ks++) {
        const int kw = ks * 8;
        uint32_t bh[4][2], bl[4][2];
#pragma unroll
        for (int nt = 0; nt < 4; nt++) {
            int n = wn * 32 + nt * 8 + g;
            const uint32_t* p = Bh + n * ld + kw + t;
            bh[nt][0] = p[0]; bh[nt][1] = p[4];
            const uint32_t* q = Bl + n * ld + kw + t;
            bl[nt][0] = q[0]; bl[nt][1] = q[4];
        }
#pragma unroll
        for (int mt = 0; mt < 4; mt++) {
            int r = wm * 64 + mt * 16 + g;
            const uint32_t* pa  = Ah + r * ld + kw + t;
            const uint32_t* pa8 = Ah + (r + 8) * ld + kw + t;
            uint32_t ah[4] = {pa[0], pa8[0], pa[4], pa8[4]};
            const uint32_t* qa  = Al + r * ld + kw + t;
            const uint32_t* qa8 = Al + (r + 8) * ld + kw + t;
            uint32_t al[4] = {qa[0], qa8[0], qa[4], qa8[4]};
#pragma unroll
            for (int nt = 0; nt < 4; nt++) {
                mma_bf16(acc[mt * 4 + nt], ah, bh[nt]);
                mma_bf16(acc[mt * 4 + nt], ah, bl[nt]);
                mma_bf16(acc[mt * 4 + nt], al, bh[nt]);
            }
        }
    }
}

__global__ __launch_bounds__(256, 1)
void cfconv_main(const float* __restrict__ r_ij,
                 const float* __restrict__ f_ij,
                 const int*   __restrict__ neighbors,
                 const float* __restrict__ pmask,
                 const float* __restrict__ fb1,
                 const float* __restrict__ fb2) {
    extern __shared__ uint32_t smw[];
    float* smf = (float*)smw;
    const int cta  = blockIdx.x;        // atoms 2*cta, 2*cta+1
    const int tid  = threadIdx.x;
    const int wid  = tid >> 5, lane = tid & 31;
    const int wm   = wid & 1, wn = wid >> 1;   // warp grid 2x4
    const uint32_t mbar = smem_u32(smw + MBAR);

    // ---- async weight image loads ----
    if (tid == 0) {
        MB_INIT(mbar + 0, 1);
        MB_INIT(mbar + 8, 1);
        FENCE_PROXY();
        MB_EXPECT_TX(mbar + 0, 2 * 18432);
        BULK_G2S(smem_u32(smw + W1_H), (const void*)g_w1h, 18432, mbar + 0);
        BULK_G2S(smem_u32(smw + W1_L), (const void*)g_w1l, 18432, mbar + 0);
        MB_EXPECT_TX(mbar + 8, 2 * 34816);
        BULK_G2S(smem_u32(smw + W2_H), (const void*)g_w2h, 34816, mbar + 8);
        BULK_G2S(smem_u32(smw + W2_L), (const void*)g_w2l, 34816, mbar + 8);
    }

    // ---- cc, biases ----
    if (tid < 128) {
        float r = r_ij[cta * 128 + tid];
        float m = pmask[cta * 128 + tid];
        float c = (r < 5.0f) ? 0.5f * (__cosf(r * 0.6283185307179586f) + 1.0f) * m : 0.0f;
        smf[SCC + tid] = c;
        smf[SB1 + tid] = fb1[tid];
        smf[SB2 + tid] = fb2[tid];
    }

    // ---- f_ij -> hi/lo bf16x2 image [row][kword], ld 36 ----
    {
        const int r = tid >> 1, half = tid & 1;
        const float4* src = (const float4*)(f_ij + (size_t)cta * 8192 + r * 64 + half * 32);
        uint32_t* dh = smw + AF_H + r * 36 + half * 16;
        uint32_t* dl = smw + AF_L + r * 36 + half * 16;
#pragma unroll
        for (int j = 0; j < 8; j++) {
            float4 v = src[j];
            uint32_t h0, l0, h1, l1;
            split2(v.x, v.y, h0, l0);
            split2(v.z, v.w, h1, l1);
            dh[2 * j] = h0; dh[2 * j + 1] = h1;
            dl[2 * j] = l0; dl[2 * j + 1] = l1;
        }
    }
    __syncthreads();   // sCC + Af visible

    // ---- ccy[col][row] = cc[row]*y[nbh[row]][col], ld 132 ----
    {
        const int n = tid & 127, half = tid >> 7;
        const int nb = neighbors[cta * 128 + n];
        const int btch = cta >> 7;
        const float ccn = smf[SCC + n];
        const float4* yr = (const float4*)(g_y + (size_t)(btch * A_ + nb) * F_ + half * 64);
        float* ccy = smf + CCY;
#pragma unroll
        for (int q = 0; q < 16; q++) {
            float4 v = yr[q];
            int c0 = half * 64 + q * 4;
            ccy[(c0 + 0) * 132 + n] = v.x * ccn;
            ccy[(c0 + 1) * 132 + n] = v.y * ccn;
            ccy[(c0 + 2) * 132 + n] = v.z * ccn;
            ccy[(c0 + 3) * 132 + n] = v.w * ccn;
        }
    }

    const int g = lane >> 2, t = lane & 3;
    float acc[16][4];

    // ---- GEMM1: H = f_ij @ W1 (+fb1 via init), K=64 ----
    MB_WAIT(mbar + 0, 0);
#pragma unroll
    for (int mt = 0; mt < 4; mt++)
#pragma unroll
        for (int nt = 0; nt < 4; nt++) {
            int j0 = wn * 32 + nt * 8 + 2 * t;
            acc[mt * 4 + nt][0] = smf[SB1 + j0];
            acc[mt * 4 + nt][1] = smf[SB1 + j0 + 1];
            acc[mt * 4 + nt][2] = smf[SB1 + j0];
            acc[mt * 4 + nt][3] = smf[SB1 + j0 + 1];
        }
    gemm_split(smw + AF_H, smw + AF_L, smw + W1_H, smw + W1_L, 36, 4, wm, wn, lane, acc);
    __syncthreads();   // all GEMM1 smem reads done (ccy writes also done)

    // ---- epilogue 1: ssp -> hi/lo H image [row][68] (overwrites AF/W1) ----
#pragma unroll
    for (int mt = 0; mt < 4; mt++) {
#pragma unroll
        for (int nt = 0; nt < 4; nt++) {
            int r  = wm * 64 + mt * 16 + g;
            int wc = wn * 16 + nt * 4 + t;
            float s0 = sspf(acc[mt * 4 + nt][0]);
            float s1 = sspf(acc[mt * 4 + nt][1]);
            float s2 = sspf(acc[mt * 4 + nt][2]);
            float s3 = sspf(acc[mt * 4 + nt][3]);
            uint32_t hi, lo;
            split2(s0, s1, hi, lo);
            smw[H_H + r * 68 + wc] = hi;
            smw[H_L + r * 68 + wc] = lo;
            split2(s2, s3, hi, lo);
            smw[H_H + (r + 8) * 68 + wc] = hi;
            smw[H_L + (r + 8) * 68 + wc] = lo;
        }
    }
    __syncthreads();   // H visible
    MB_WAIT(mbar + 8, 0);

    // ---- GEMM2: W = H @ W2 (+fb2 via init), K=128 ----
#pragma unroll
    for (int mt = 0; mt < 4; mt++)
#pragma unroll
        for (int nt = 0; nt < 4; nt++) {
            int j0 = wn * 32 + nt * 8 + 2 * t;
            acc[mt * 4 + nt][0] = smf[SB2 + j0];
            acc[mt * 4 + nt][1] = smf[SB2 + j0 + 1];
            acc[mt * 4 + nt][2] = smf[SB2 + j0];
            acc[mt * 4 + nt][3] = smf[SB2 + j0 + 1];
        }
    gemm_split(smw + H_H, smw + H_L, smw + W2_H, smw + W2_L, 68, 8, wm, wn, lane, acc);

    // ---- epilogue 2: agg[f] = sum_rows W[r][f] * ccy[f][r] ----
    {
        const float* ccy = smf + CCY;
        float part[4][2];
#pragma unroll
        for (int nt = 0; nt < 4; nt++) { part[nt][0] = 0.f; part[nt][1] = 0.f; }
#pragma unroll
        for (int mt = 0; mt < 4; mt++) {
            int r0 = wm * 64 + mt * 16 + g;
            int r1 = r0 + 8;
#pragma unroll
            for (int nt = 0; nt < 4; nt++) {
                int j0 = wn * 32 + nt * 8 + 2 * t;
                int j1 = j0 + 1;
                part[nt][0] += acc[mt * 4 + nt][0] * ccy[j0 * 132 + r0]
                             + acc[mt * 4 + nt][2] * ccy[j0 * 132 + r1];
                part[nt][1] += acc[mt * 4 + nt][1] * ccy[j1 * 132 + r0]
                             + acc[mt * 4 + nt][3] * ccy[j1 * 132 + r1];
            }
        }
#pragma unroll
        for (int nt = 0; nt < 4; nt++)
#pragma unroll
            for (int bcol = 0; bcol < 2; bcol++) {
                float v = part[nt][bcol];
                v += __shfl_xor_sync(0xffffffffu, v, 4);
                v += __shfl_xor_sync(0xffffffffu, v, 8);
                v += __shfl_xor_sync(0xffffffffu, v, 16);
                part[nt][bcol] = v;
            }
        if (g == 0) {
#pragma unroll
            for (int nt = 0; nt < 4; nt++) {
                int j0 = wn * 32 + nt * 8 + 2 * t;
                smf[SAGG + wm * 128 + j0]     = part[nt][0];
                smf[SAGG + wm * 128 + j0 + 1] = part[nt][1];
            }
        }
    }
    __syncthreads();
    {
        const int atom = tid >> 7, c = tid & 127;
        g_agg[((size_t)cta * 2 + atom) * F_ + c] = smf[SAGG + atom * 128 + c];
    }
    __syncthreads();
    if (tid == 0) { MB_INVAL(mbar + 0); MB_INVAL(mbar + 8); }
}

// ---------------------------------------------------------------------------
extern "C" void kernel_launch(void* const* d_in, const int* in_sizes, int n_in,
                              void* d_out, int out_size) {
    const float* x        = (const float*)d_in[0];
    const float* r_ij     = (const float*)d_in[1];
    const float* f_ij     = (const float*)d_in[2];
    const int*   neighbors= (const int*)  d_in[3];
    const float* pmask    = (const float*)d_in[4];
    const float* fw1      = (const float*)d_in[5];
    const float* fb1      = (const float*)d_in[6];
    const float* fw2      = (const float*)d_in[7];
    const float* fb2      = (const float*)d_in[8];
    const float* w_in2f   = (const float*)d_in[9];
    const float* w_f2out  = (const float*)d_in[10];
    const float* b_f2out  = (const float*)d_in[11];
    float* out = (float*)d_out;

    cudaFuncSetAttribute(cfconv_main,
                         cudaFuncAttributeMaxDynamicSharedMemorySize, SMEM_BYTES);

    float* yptr;   cudaGetSymbolAddress((void**)&yptr, g_y);
    float* aggptr; cudaGetSymbolAddress((void**)&aggptr, g_agg);

    weights_img_kernel<<<48, 256>>>(fw1, fw2);
    small_gemm<<<ROWS_TOTAL / 32, 256>>>(x, w_in2f, nullptr, yptr, 0);
    cfconv_main<<<ROWS_TOTAL / 2, 256, SMEM_BYTES>>>(
        r_ij, f_ij, neighbors, pmask, fb1, fb2);
    small_gemm<<<ROWS_TOTAL / 32, 256>>>(aggptr, w_f2out, b_f2out, out, 1);
}